// round 8
// baseline (speedup 1.0000x reference)
#include <cuda_runtime.h>
#include <cuda_fp16.h>
#include <cstdint>

#define NN 50000
#define DF 256
#define NF 192
#define EF 64
#define ME 800000
#define OF 2048
#define NDEPTH 3

// static device scratch (no allocations anywhere)
__device__ float g_A[(size_t)NN * DF];
__device__ float g_V[(size_t)NN * DF];
__device__ float g_L[(size_t)NN * OF];

#define SASTR 40  // smem row stride in halfs: A/B fragment lds.b32 are bank-conflict-free

__device__ __forceinline__ void mma16816(float* c, const uint32_t* a, const uint32_t* b) {
    asm volatile(
        "mma.sync.aligned.m16n8k16.row.col.f32.f16.f16.f32 "
        "{%0,%1,%2,%3}, {%4,%5,%6,%7}, {%8,%9}, {%0,%1,%2,%3};"
        : "+f"(c[0]), "+f"(c[1]), "+f"(c[2]), "+f"(c[3])
        : "r"(a[0]), "r"(a[1]), "r"(a[2]), "r"(a[3]), "r"(b[0]), "r"(b[1]));
}

// C[M, Ng] = A[M, 256] @ W[256, Ng] + bias ; fp16 2-term split, fp32 accum.
__global__ __launch_bounds__(256, 1)
void gemm_tc(const float* __restrict__ A, const float* __restrict__ W,
             const float* __restrict__ bias, float* __restrict__ C,
             int M, int Ng) {
    __shared__ __half Ah[128 * SASTR], Al[128 * SASTR];
    __shared__ __half Bh[128 * SASTR], Bl[128 * SASTR];
    int tid = threadIdx.x, lane = tid & 31, wid = tid >> 5;
    int g = lane >> 2, t = lane & 3;
    int wm = (wid & 3) * 32, wn = (wid >> 2) * 64;
    int row0 = blockIdx.y * 128, col0 = blockIdx.x * 128;

    float acc[2][8][4];
#pragma unroll
    for (int i = 0; i < 2; i++)
#pragma unroll
        for (int j = 0; j < 8; j++)
#pragma unroll
            for (int k = 0; k < 4; k++) acc[i][j][k] = 0.f;

    float4 av[4];   // staged A tile slice (gmem -> regs)
    float  bv[16];  // staged B tile slice
    const float* Wp = W + col0;

    auto stage = [&](int it) {
        int k0 = it * 32;
#pragma unroll
        for (int q = 0; q < 4; q++) {
            int idx = tid + q * 256;
            int r = idx >> 3, kq = idx & 7;
            av[q] = (row0 + r < M)
                        ? *(const float4*)&A[(size_t)(row0 + r) * DF + k0 + kq * 4]
                        : make_float4(0.f, 0.f, 0.f, 0.f);
        }
#pragma unroll
        for (int q = 0; q < 8; q++) {
            int idx = tid + q * 256;
            int n = idx & 127, k2 = idx >> 7;
            bv[2 * q]     = Wp[(size_t)(k0 + 2 * k2) * Ng + n];
            bv[2 * q + 1] = Wp[(size_t)(k0 + 2 * k2 + 1) * Ng + n];
        }
    };

    auto commit = [&] {
#pragma unroll
        for (int q = 0; q < 4; q++) {
            int idx = tid + q * 256;
            int r = idx >> 3, kq = idx & 7;
            float4 v = av[q];
            __half hx = __float2half_rn(v.x), hy = __float2half_rn(v.y);
            __half hz = __float2half_rn(v.z), hw = __float2half_rn(v.w);
            __half lx = __float2half_rn(v.x - __half2float(hx));
            __half ly = __float2half_rn(v.y - __half2float(hy));
            __half lz = __float2half_rn(v.z - __half2float(hz));
            __half lw = __float2half_rn(v.w - __half2float(hw));
            __half2* ph = (__half2*)&Ah[r * SASTR + kq * 4];
            ph[0] = __halves2half2(hx, hy); ph[1] = __halves2half2(hz, hw);
            __half2* pl = (__half2*)&Al[r * SASTR + kq * 4];
            pl[0] = __halves2half2(lx, ly); pl[1] = __halves2half2(lz, lw);
        }
#pragma unroll
        for (int q = 0; q < 8; q++) {
            int idx = tid + q * 256;
            int n = idx & 127, k2 = idx >> 7;
            float f0 = bv[2 * q], f1 = bv[2 * q + 1];
            __half h0 = __float2half_rn(f0), h1 = __float2half_rn(f1);
            __half l0 = __float2half_rn(f0 - __half2float(h0));
            __half l1 = __float2half_rn(f1 - __half2float(h1));
            *(__half2*)&Bh[n * SASTR + 2 * k2] = __halves2half2(h0, h1);
            *(__half2*)&Bl[n * SASTR + 2 * k2] = __halves2half2(l0, l1);
        }
    };

    auto compute = [&] {
#pragma unroll
        for (int ks = 0; ks < 2; ks++) {
            uint32_t ah[2][4], al[2][4];
#pragma unroll
            for (int mt = 0; mt < 2; mt++) {
                int r = wm + mt * 16;
                int o0 = (r + g) * SASTR + ks * 16 + 2 * t;
                int o1 = (r + g + 8) * SASTR + ks * 16 + 2 * t;
                ah[mt][0] = *(const uint32_t*)&Ah[o0];
                ah[mt][1] = *(const uint32_t*)&Ah[o1];
                ah[mt][2] = *(const uint32_t*)&Ah[o0 + 8];
                ah[mt][3] = *(const uint32_t*)&Ah[o1 + 8];
                al[mt][0] = *(const uint32_t*)&Al[o0];
                al[mt][1] = *(const uint32_t*)&Al[o1];
                al[mt][2] = *(const uint32_t*)&Al[o0 + 8];
                al[mt][3] = *(const uint32_t*)&Al[o1 + 8];
            }
#pragma unroll
            for (int nt = 0; nt < 8; nt++) {
                int n = wn + nt * 8 + g;
                int ob = n * SASTR + ks * 16 + 2 * t;
                uint32_t bh[2], bl[2];
                bh[0] = *(const uint32_t*)&Bh[ob];
                bh[1] = *(const uint32_t*)&Bh[ob + 8];
                bl[0] = *(const uint32_t*)&Bl[ob];
                bl[1] = *(const uint32_t*)&Bl[ob + 8];
#pragma unroll
                for (int mt = 0; mt < 2; mt++) {
                    mma16816(acc[mt][nt], ah[mt], bh);  // hi*hi
                    mma16816(acc[mt][nt], ah[mt], bl);  // hi*lo
                    mma16816(acc[mt][nt], al[mt], bh);  // lo*hi
                }
            }
        }
    };

    stage(0);
#pragma unroll 1
    for (int it = 0; it < 8; it++) {
        __syncthreads();          // previous compute done; smem reusable
        commit();
        __syncthreads();
        if (it < 7) stage(it + 1);  // prefetch next tile while computing
        compute();
    }

    // epilogue: acc + bias -> C
#pragma unroll
    for (int mt = 0; mt < 2; mt++) {
#pragma unroll
        for (int i = 0; i < 2; i++) {
            int r = row0 + wm + mt * 16 + g + i * 8;
            if (r < M) {
#pragma unroll
                for (int nt = 0; nt < 8; nt++) {
                    int cc = col0 + wn + nt * 8 + 2 * t;
                    float2 v;
                    v.x = acc[mt][nt][i * 2 + 0] + bias[cc];
                    v.y = acc[mt][nt][i * 2 + 1] + bias[cc + 1];
                    *(float2*)&C[(size_t)r * Ng + cc] = v;
                }
            }
        }
    }
}

// ---------------- elementwise / graph kernels ----------------
__global__ void init_attr(const float* __restrict__ na, float* __restrict__ A) {
    int i = blockIdx.x * blockDim.x + threadIdx.x;
    if (i >= NN * DF) return;
    int r = i >> 8, c = i & 255;
    A[i] = (c < NF) ? na[r * NF + c] : 0.f;
}

__global__ void zero_fp(float* __restrict__ fp) {
    int i = blockIdx.x * blockDim.x + threadIdx.x;
    if (i < OF) fp[i] = 0.f;
}

__global__ void copyV(const float4* __restrict__ A, float4* __restrict__ V) {
    int i = blockIdx.x * blockDim.x + threadIdx.x;
    if (i < NN * (DF / 4)) V[i] = A[i];
}

__global__ void edge_scatter(const float* __restrict__ A, const float* __restrict__ EA,
                             const int* __restrict__ src, const int* __restrict__ dst,
                             float* __restrict__ V) {
    int idx = blockIdx.x * blockDim.x + threadIdx.x;
    if (idx >= ME * (DF / 4)) return;
    int e = idx >> 6, c = idx & 63;
    int s = src[e], d = dst[e];
    float4 v = *(const float4*)&A[(size_t)s * DF + c * 4];
    if (c >= NF / 4) {
        float4 ev = *(const float4*)&EA[(size_t)e * EF + (c - NF / 4) * 4];
        v.x += ev.x; v.y += ev.y; v.z += ev.z; v.w += ev.w;
    }
    float* p = &V[(size_t)d * DF + c * 4];
    atomicAdd(p, v.x); atomicAdd(p + 1, v.y);
    atomicAdd(p + 2, v.z); atomicAdd(p + 3, v.w);
}

__global__ __launch_bounds__(256)
void softmax_acc(const float* __restrict__ L, float* __restrict__ fp, int M) {
    __shared__ float sacc[OF];
    __shared__ float red[8];
    int tid = threadIdx.x;
    for (int c = tid; c < OF; c += 256) sacc[c] = 0.f;
    __syncthreads();
    int r0 = blockIdx.x * 32;
    int rend = min(r0 + 32, M);
    for (int r = r0; r < rend; r++) {
        const float* row = L + (size_t)r * OF;
        float v[8];
        float mx = -1e30f;
#pragma unroll
        for (int j = 0; j < 8; j++) { v[j] = row[tid + j * 256]; mx = fmaxf(mx, v[j]); }
        for (int o = 16; o; o >>= 1) mx = fmaxf(mx, __shfl_xor_sync(~0u, mx, o));
        if ((tid & 31) == 0) red[tid >> 5] = mx;
        __syncthreads();
        float m = fmaxf(fmaxf(fmaxf(red[0], red[1]), fmaxf(red[2], red[3])),
                        fmaxf(fmaxf(red[4], red[5]), fmaxf(red[6], red[7])));
        float s = 0.f;
#pragma unroll
        for (int j = 0; j < 8; j++) { v[j] = __expf(v[j] - m); s += v[j]; }
        for (int o = 16; o; o >>= 1) s += __shfl_xor_sync(~0u, s, o);
        __syncthreads();
        if ((tid & 31) == 0) red[tid >> 5] = s;
        __syncthreads();
        float inv = 1.f / (red[0] + red[1] + red[2] + red[3] +
                           red[4] + red[5] + red[6] + red[7]);
#pragma unroll
        for (int j = 0; j < 8; j++) sacc[tid + j * 256] += v[j] * inv;
        __syncthreads();
    }
    for (int c = tid; c < OF; c += 256) atomicAdd(&fp[c], sacc[c]);
}

extern "C" void kernel_launch(void* const* d_in, const int* in_sizes, int n_in,
                              void* d_out, int out_size) {
    const float* node_attr = (const float*)d_in[0];
    const float* edge_attr = (const float*)d_in[1];
    const int*   edge_src  = (const int*)d_in[2];
    const int*   edge_dst  = (const int*)d_in[3];
    const float* W_inner   = (const float*)d_in[4];
    const float* b_inner   = (const float*)d_in[5];
    const float* W_output  = (const float*)d_in[6];
    const float* b_output  = (const float*)d_in[7];
    float* fp = (float*)d_out;

    float *A, *V, *L;
    cudaGetSymbolAddress((void**)&A, g_A);
    cudaGetSymbolAddress((void**)&V, g_V);
    cudaGetSymbolAddress((void**)&L, g_L);

    init_attr<<<(NN * DF + 255) / 256, 256>>>(node_attr, A);
    zero_fp<<<(OF + 255) / 256, 256>>>(fp);

    dim3 gOut(OF / 128, (NN + 127) / 128);
    dim3 gIn(DF / 128, (NN + 127) / 128);
    int smBlocks = (NN + 31) / 32;

    for (int d = 0; d <= NDEPTH; d++) {
        gemm_tc<<<gOut, 256>>>(A, W_output + (size_t)d * DF * OF,
                               b_output + (size_t)d * OF, L, NN, OF);
        softmax_acc<<<smBlocks, 256>>>(L, fp, NN);
        if (d < NDEPTH) {
            copyV<<<(NN * DF / 4 + 255) / 256, 256>>>((const float4*)A, (float4*)V);
            edge_scatter<<<(ME * (DF / 4) + 255) / 256, 256>>>(A, edge_attr,
                                                               edge_src, edge_dst, V);
            gemm_tc<<<gIn, 256>>>(V, W_inner + (size_t)d * DF * DF,
                                  b_inner + (size_t)d * DF, A, NN, DF);
        }
    }
}

// round 9
// speedup vs baseline: 1.1229x; 1.1229x over previous
#include <cuda_runtime.h>
#include <cuda_fp16.h>
#include <cstdint>

#define NN 50000
#define DF 256
#define NF 192
#define EF 64
#define ME 800000
#define OF 2048
#define NDEPTH 3

// static device scratch (no allocations anywhere)
__device__ float g_A[(size_t)NN * DF];
__device__ float g_V[(size_t)NN * DF];
__device__ float g_L[(size_t)NN * OF];
__device__ __half g_Ah[(size_t)NN * DF];
__device__ __half g_Al[(size_t)NN * DF];
#define WI_OFF ((size_t)4 * OF * DF)
__device__ __half g_Wth[WI_OFF + (size_t)NDEPTH * DF * DF];
__device__ __half g_Wtl[WI_OFF + (size_t)NDEPTH * DF * DF];

#define SASTR 40  // smem row stride in halfs (80 B): conflict-free frag lds + aligned cp.async

__device__ __forceinline__ uint32_t smem_u32(const void* p) {
    uint32_t a;
    asm("{ .reg .u64 t; cvta.to.shared.u64 t, %1; cvt.u32.u64 %0, t; }" : "=r"(a) : "l"(p));
    return a;
}
__device__ __forceinline__ void cpasync16(uint32_t dst, const void* src, int sz) {
    asm volatile("cp.async.cg.shared.global [%0], [%1], 16, %2;"
                 :: "r"(dst), "l"(src), "r"(sz) : "memory");
}
__device__ __forceinline__ void mma16816(float* c, const uint32_t* a, const uint32_t* b) {
    asm volatile(
        "mma.sync.aligned.m16n8k16.row.col.f32.f16.f16.f32 "
        "{%0,%1,%2,%3}, {%4,%5,%6,%7}, {%8,%9}, {%0,%1,%2,%3};"
        : "+f"(c[0]), "+f"(c[1]), "+f"(c[2]), "+f"(c[3])
        : "r"(a[0]), "r"(a[1]), "r"(a[2]), "r"(a[3]), "r"(b[0]), "r"(b[1]));
}

// dynamic smem layout (halves): buf b at b*20480; Ah:0 Al:5120 Bh:10240 Bl:15360
#define GH_SMEM 81920

// C[M,Ng] = A[M,256] @ W[256,Ng] + bias, from pre-split half inputs.
// Bt* are W transposed: Bt[n][k], row-major with K=256.
__global__ __launch_bounds__(256, 2)
void gemm_h(const __half* __restrict__ Ahg, const __half* __restrict__ Alg,
            const __half* __restrict__ Bth, const __half* __restrict__ Btl,
            const float* __restrict__ bias, float* __restrict__ C, int M, int Ng) {
    extern __shared__ __half sm[];
    uint32_t sb = smem_u32(sm);
    int tid = threadIdx.x, lane = tid & 31, wid = tid >> 5;
    int g = lane >> 2, t = lane & 3;
    int wm = (wid & 3) * 32, wn = (wid >> 2) * 64;
    int row0 = blockIdx.y * 128, col0 = blockIdx.x * 128;

    float acc[2][8][4];
#pragma unroll
    for (int i = 0; i < 2; i++)
#pragma unroll
        for (int j = 0; j < 8; j++)
#pragma unroll
            for (int k = 0; k < 4; k++) acc[i][j][k] = 0.f;

    auto issue = [&](int it) {
        int b = it & 1, k0 = it * 32;
        uint32_t bufb = sb + b * 40960;
#pragma unroll
        for (int q = 0; q < 2; q++) {
            int idx = tid + q * 256;
            int r = idx >> 2, c4 = idx & 3;
            int rr = row0 + r;
            int p = (rr < M) ? 16 : 0;
            if (rr >= M) rr = M - 1;
            size_t so = (size_t)rr * DF + k0 + c4 * 8;
            uint32_t d = bufb + r * 80 + c4 * 16;
            cpasync16(d, Ahg + so, p);
            cpasync16(d + 10240, Alg + so, p);
        }
#pragma unroll
        for (int q = 0; q < 2; q++) {
            int idx = tid + q * 256;
            int n = idx >> 2, c4 = idx & 3;
            size_t so = (size_t)(col0 + n) * DF + k0 + c4 * 8;
            uint32_t d = bufb + 20480 + n * 80 + c4 * 16;
            cpasync16(d, Bth + so, 16);
            cpasync16(d + 10240, Btl + so, 16);
        }
        asm volatile("cp.async.commit_group;" ::: "memory");
    };

    auto compute = [&](int b) {
        const __half* Ahs = sm + b * 20480;
        const __half* Als = Ahs + 5120;
        const __half* Bhs = Ahs + 10240;
        const __half* Bls = Ahs + 15360;
#pragma unroll
        for (int ks = 0; ks < 2; ks++) {
            uint32_t ah[2][4], al[2][4];
#pragma unroll
            for (int mt = 0; mt < 2; mt++) {
                int r = wm + mt * 16;
                int o0 = (r + g) * SASTR + ks * 16 + 2 * t;
                int o1 = (r + g + 8) * SASTR + ks * 16 + 2 * t;
                ah[mt][0] = *(const uint32_t*)&Ahs[o0];
                ah[mt][1] = *(const uint32_t*)&Ahs[o1];
                ah[mt][2] = *(const uint32_t*)&Ahs[o0 + 8];
                ah[mt][3] = *(const uint32_t*)&Ahs[o1 + 8];
                al[mt][0] = *(const uint32_t*)&Als[o0];
                al[mt][1] = *(const uint32_t*)&Als[o1];
                al[mt][2] = *(const uint32_t*)&Als[o0 + 8];
                al[mt][3] = *(const uint32_t*)&Als[o1 + 8];
            }
#pragma unroll
            for (int nt = 0; nt < 8; nt++) {
                int ob = (wn + nt * 8 + g) * SASTR + ks * 16 + 2 * t;
                uint32_t bh[2], bl[2];
                bh[0] = *(const uint32_t*)&Bhs[ob];
                bh[1] = *(const uint32_t*)&Bhs[ob + 8];
                bl[0] = *(const uint32_t*)&Bls[ob];
                bl[1] = *(const uint32_t*)&Bls[ob + 8];
#pragma unroll
                for (int mt = 0; mt < 2; mt++) {
                    mma16816(acc[mt][nt], ah[mt], bh);  // hi*hi
                    mma16816(acc[mt][nt], ah[mt], bl);  // hi*lo
                    mma16816(acc[mt][nt], al[mt], bh);  // lo*hi
                }
            }
        }
    };

    issue(0);
#pragma unroll 1
    for (int it = 0; it < 8; it++) {
        asm volatile("cp.async.wait_group 0;" ::: "memory");
        __syncthreads();
        if (it < 7) issue(it + 1);  // overlap next load with this compute
        compute(it & 1);
    }

#pragma unroll
    for (int mt = 0; mt < 2; mt++) {
#pragma unroll
        for (int i = 0; i < 2; i++) {
            int r = row0 + wm + mt * 16 + g + i * 8;
            if (r < M) {
#pragma unroll
                for (int nt = 0; nt < 8; nt++) {
                    int cc = col0 + wn + nt * 8 + 2 * t;
                    float2 v;
                    v.x = acc[mt][nt][i * 2 + 0] + bias[cc];
                    v.y = acc[mt][nt][i * 2 + 1] + bias[cc + 1];
                    *(float2*)&C[(size_t)r * Ng + cc] = v;
                }
            }
        }
    }
}

// W [256, N] -> transposed hi/lo halves Wt[n][k] (K=256 row stride)
__global__ void wconvT(const float* __restrict__ W, __half* __restrict__ Th,
                       __half* __restrict__ Tl, int N) {
    __shared__ float tb[32][33];
    int k0 = blockIdx.y * 32, n0 = blockIdx.x * 32;
    for (int i = threadIdx.y; i < 32; i += 8)
        tb[i][threadIdx.x] = W[(size_t)(k0 + i) * N + n0 + threadIdx.x];
    __syncthreads();
    for (int i = threadIdx.y; i < 32; i += 8) {
        int n = n0 + i, k = k0 + threadIdx.x;
        float v = tb[threadIdx.x][i];
        __half h = __float2half_rn(v);
        Th[(size_t)n * 256 + k] = h;
        Tl[(size_t)n * 256 + k] = __float2half_rn(v - __half2float(h));
    }
}

// X fp32 -> hi/lo halves (vectorized)
__global__ void convAH(const float4* __restrict__ X, uint2* __restrict__ H,
                       uint2* __restrict__ Lo) {
    int i = blockIdx.x * blockDim.x + threadIdx.x;
    if (i >= NN * DF / 4) return;
    float4 v = X[i];
    __half hx = __float2half_rn(v.x), hy = __float2half_rn(v.y);
    __half hz = __float2half_rn(v.z), hw = __float2half_rn(v.w);
    __half2 h01 = __halves2half2(hx, hy), h23 = __halves2half2(hz, hw);
    __half2 l01 = __halves2half2(__float2half_rn(v.x - __half2float(hx)),
                                 __float2half_rn(v.y - __half2float(hy)));
    __half2 l23 = __halves2half2(__float2half_rn(v.z - __half2float(hz)),
                                 __float2half_rn(v.w - __half2float(hw)));
    uint2 ho, lo;
    ho.x = *(uint32_t*)&h01; ho.y = *(uint32_t*)&h23;
    lo.x = *(uint32_t*)&l01; lo.y = *(uint32_t*)&l23;
    H[i] = ho; Lo[i] = lo;
}

// ---------------- elementwise / graph kernels ----------------
__global__ void init_attr(const float* __restrict__ na, float* __restrict__ A) {
    int i = blockIdx.x * blockDim.x + threadIdx.x;
    if (i >= NN * DF) return;
    int r = i >> 8, c = i & 255;
    A[i] = (c < NF) ? na[r * NF + c] : 0.f;
}

__global__ void zero_fp(float* __restrict__ fp) {
    int i = blockIdx.x * blockDim.x + threadIdx.x;
    if (i < OF) fp[i] = 0.f;
}

__global__ void copyV(const float4* __restrict__ A, float4* __restrict__ V) {
    int i = blockIdx.x * blockDim.x + threadIdx.x;
    if (i < NN * (DF / 4)) V[i] = A[i];
}

__global__ void edge_scatter(const float* __restrict__ A, const float* __restrict__ EA,
                             const int* __restrict__ src, const int* __restrict__ dst,
                             float* __restrict__ V) {
    int idx = blockIdx.x * blockDim.x + threadIdx.x;
    if (idx >= ME * (DF / 4)) return;
    int e = idx >> 6, c = idx & 63;
    int s = src[e], d = dst[e];
    float4 v = *(const float4*)&A[(size_t)s * DF + c * 4];
    if (c >= NF / 4) {
        float4 ev = *(const float4*)&EA[(size_t)e * EF + (c - NF / 4) * 4];
        v.x += ev.x; v.y += ev.y; v.z += ev.z; v.w += ev.w;
    }
    float* p = &V[(size_t)d * DF + c * 4];
    atomicAdd(p, v.x); atomicAdd(p + 1, v.y);
    atomicAdd(p + 2, v.z); atomicAdd(p + 3, v.w);
}

__global__ __launch_bounds__(256)
void softmax_acc(const float* __restrict__ L, float* __restrict__ fp, int M) {
    __shared__ float sacc[OF];
    __shared__ float red[8];
    int tid = threadIdx.x;
    for (int c = tid; c < OF; c += 256) sacc[c] = 0.f;
    __syncthreads();
    int r0 = blockIdx.x * 32;
    int rend = min(r0 + 32, M);
    for (int r = r0; r < rend; r++) {
        const float* row = L + (size_t)r * OF;
        float v[8];
        float mx = -1e30f;
#pragma unroll
        for (int j = 0; j < 8; j++) { v[j] = row[tid + j * 256]; mx = fmaxf(mx, v[j]); }
        for (int o = 16; o; o >>= 1) mx = fmaxf(mx, __shfl_xor_sync(~0u, mx, o));
        if ((tid & 31) == 0) red[tid >> 5] = mx;
        __syncthreads();
        float m = fmaxf(fmaxf(fmaxf(red[0], red[1]), fmaxf(red[2], red[3])),
                        fmaxf(fmaxf(red[4], red[5]), fmaxf(red[6], red[7])));
        float s = 0.f;
#pragma unroll
        for (int j = 0; j < 8; j++) { v[j] = __expf(v[j] - m); s += v[j]; }
        for (int o = 16; o; o >>= 1) s += __shfl_xor_sync(~0u, s, o);
        __syncthreads();
        if ((tid & 31) == 0) red[tid >> 5] = s;
        __syncthreads();
        float inv = 1.f / (red[0] + red[1] + red[2] + red[3] +
                           red[4] + red[5] + red[6] + red[7]);
#pragma unroll
        for (int j = 0; j < 8; j++) sacc[tid + j * 256] += v[j] * inv;
        __syncthreads();
    }
    for (int c = tid; c < OF; c += 256) atomicAdd(&fp[c], sacc[c]);
}

extern "C" void kernel_launch(void* const* d_in, const int* in_sizes, int n_in,
                              void* d_out, int out_size) {
    const float* node_attr = (const float*)d_in[0];
    const float* edge_attr = (const float*)d_in[1];
    const int*   edge_src  = (const int*)d_in[2];
    const int*   edge_dst  = (const int*)d_in[3];
    const float* W_inner   = (const float*)d_in[4];
    const float* b_inner   = (const float*)d_in[5];
    const float* W_output  = (const float*)d_in[6];
    const float* b_output  = (const float*)d_in[7];
    float* fp = (float*)d_out;

    float *A, *V, *L;
    __half *Ah, *Al, *Wth, *Wtl;
    cudaGetSymbolAddress((void**)&A, g_A);
    cudaGetSymbolAddress((void**)&V, g_V);
    cudaGetSymbolAddress((void**)&L, g_L);
    cudaGetSymbolAddress((void**)&Ah, g_Ah);
    cudaGetSymbolAddress((void**)&Al, g_Al);
    cudaGetSymbolAddress((void**)&Wth, g_Wth);
    cudaGetSymbolAddress((void**)&Wtl, g_Wtl);

    static int cfg_done = 0;
    if (!cfg_done) {
        cudaFuncSetAttribute(gemm_h, cudaFuncAttributeMaxDynamicSharedMemorySize, GH_SMEM);
        cfg_done = 1;
    }

    // convert + transpose weights (once per replay; cheap)
    for (int d = 0; d <= NDEPTH; d++)
        wconvT<<<dim3(OF / 32, 8), dim3(32, 8)>>>(W_output + (size_t)d * DF * OF,
                                                  Wth + (size_t)d * OF * DF,
                                                  Wtl + (size_t)d * OF * DF, OF);
    for (int d = 0; d < NDEPTH; d++)
        wconvT<<<dim3(DF / 32, 8), dim3(32, 8)>>>(W_inner + (size_t)d * DF * DF,
                                                  Wth + WI_OFF + (size_t)d * DF * DF,
                                                  Wtl + WI_OFF + (size_t)d * DF * DF, DF);

    init_attr<<<(NN * DF + 255) / 256, 256>>>(node_attr, A);
    zero_fp<<<(OF + 255) / 256, 256>>>(fp);

    dim3 gOut(OF / 128, (NN + 127) / 128);
    dim3 gIn(DF / 128, (NN + 127) / 128);
    int smBlocks = (NN + 31) / 32;
    int cvGrid = (NN * DF / 4 + 255) / 256;

    for (int d = 0; d <= NDEPTH; d++) {
        convAH<<<cvGrid, 256>>>((const float4*)A, (uint2*)Ah, (uint2*)Al);
        gemm_h<<<gOut, 256, GH_SMEM>>>(Ah, Al, Wth + (size_t)d * OF * DF,
                                       Wtl + (size_t)d * OF * DF,
                                       b_output + (size_t)d * OF, L, NN, OF);
        softmax_acc<<<smBlocks, 256>>>(L, fp, NN);
        if (d < NDEPTH) {
            copyV<<<(NN * DF / 4 + 255) / 256, 256>>>((const float4*)A, (float4*)V);
            edge_scatter<<<(ME * (DF / 4) + 255) / 256, 256>>>(A, edge_attr,
                                                               edge_src, edge_dst, V);
            convAH<<<cvGrid, 256>>>((const float4*)V, (uint2*)Ah, (uint2*)Al);
            gemm_h<<<gIn, 256, GH_SMEM>>>(Ah, Al, Wth + WI_OFF + (size_t)d * DF * DF,
                                          Wtl + WI_OFF + (size_t)d * DF * DF,
                                          b_inner + (size_t)d * DF, A, NN, DF);
        }
    }
}